// round 6
// baseline (speedup 1.0000x reference)
#include <cuda_runtime.h>
#include <cuda_bf16.h>
#include <cstddef>

// Problem constants: N=50000, DEG=32, E=N*32, F=64, K=3, DIM=2, L=3
#define MAXN 50000
#define FDIM 64
#define KF   192        // K * F
#define NCHUNK 3

// Scratch (device globals — no allocation in kernel_launch)
__device__ float g_buf[(size_t)MAXN * KF];
__device__ float h_bufA[(size_t)MAXN * FDIM];
__device__ float h_bufB[(size_t)MAXN * FDIM];

// Packed fp32x2 FMA (sm_103a FFMA2 — only reachable via PTX)
#define FMA_F32X2(d, a, b, c) \
    asm("fma.rn.f32x2 %0, %1, %2, %3;" : "=l"(d) : "l"(a), "l"(b), "l"(c))
#define UNPACK2(lo, hi, v) \
    asm("mov.b64 {%0, %1}, %2;" : "=f"(lo), "=f"(hi) : "l"(v))

// ---------------------------------------------------------------------------
// Aggregation kernel (chunked): one warp per destination node in [ns, ne).
//   g[i, k*64+f] = sum_e w_k(e) * h[colind[e], f]
// ---------------------------------------------------------------------------
__global__ __launch_bounds__(256)
void agg_kernel(const float* __restrict__ h,
                const float* __restrict__ pseudo,   // [E,2]
                const int*   __restrict__ rowptr,   // [N+1]
                const int*   __restrict__ colind,   // [E]
                const float* __restrict__ pW,       // [2,2]
                const float* __restrict__ pb,       // [2]
                const float* __restrict__ mu,       // [K,2]
                const float* __restrict__ isg,      // [K,2]
                float* __restrict__ g, int ns, int ne)
{
    __shared__ float w0s[8][32], w1s[8][32], w2s[8][32];
    __shared__ int   ss[8][32];

    const int wid = threadIdx.x >> 5;
    const int lid = threadIdx.x & 31;
    const int node = ns + blockIdx.x * 8 + wid;
    if (node >= ne) return;

    const float W00 = pW[0], W01 = pW[1], W10 = pW[2], W11 = pW[3];
    const float b0 = pb[0], b1 = pb[1];
    const float m00 = mu[0], m01 = mu[1], m10 = mu[2], m11 = mu[3], m20 = mu[4], m21 = mu[5];
    const float s00 = isg[0]*isg[0], s01 = isg[1]*isg[1];
    const float s10 = isg[2]*isg[2], s11 = isg[3]*isg[3];
    const float s20 = isg[4]*isg[4], s21 = isg[5]*isg[5];

    const int e0 = rowptr[node], e1 = rowptr[node + 1];

    float a0x = 0.f, a0y = 0.f, a1x = 0.f, a1y = 0.f, a2x = 0.f, a2y = 0.f;
    const float2* __restrict__ ps2 = (const float2*)pseudo;

    for (int base = e0; base < e1; base += 32) {
        const int cnt = min(32, e1 - base);
        if (lid < cnt) {
            const int e = base + lid;
            float2 ps = __ldg(&ps2[e]);
            float u0 = tanhf(fmaf(ps.y, W10, fmaf(ps.x, W00, b0)));
            float u1 = tanhf(fmaf(ps.y, W11, fmaf(ps.x, W01, b1)));
            float d0, d1;
            d0 = u0 - m00; d1 = u1 - m01;
            w0s[wid][lid] = __expf(-0.5f * (d0*d0*s00 + d1*d1*s01));
            d0 = u0 - m10; d1 = u1 - m11;
            w1s[wid][lid] = __expf(-0.5f * (d0*d0*s10 + d1*d1*s11));
            d0 = u0 - m20; d1 = u1 - m21;
            w2s[wid][lid] = __expf(-0.5f * (d0*d0*s20 + d1*d1*s21));
            ss[wid][lid] = __ldg(&colind[e]);
        }
        __syncwarp();
        if (cnt == 32) {
            #pragma unroll 8
            for (int t = 0; t < 32; t++) {
                const float2 hv = __ldg((const float2*)(h + (size_t)ss[wid][t] * FDIM) + lid);
                const float w0 = w0s[wid][t], w1 = w1s[wid][t], w2 = w2s[wid][t];
                a0x = fmaf(w0, hv.x, a0x); a0y = fmaf(w0, hv.y, a0y);
                a1x = fmaf(w1, hv.x, a1x); a1y = fmaf(w1, hv.y, a1y);
                a2x = fmaf(w2, hv.x, a2x); a2y = fmaf(w2, hv.y, a2y);
            }
        } else {
            for (int t = 0; t < cnt; t++) {
                const float2 hv = __ldg((const float2*)(h + (size_t)ss[wid][t] * FDIM) + lid);
                const float w0 = w0s[wid][t], w1 = w1s[wid][t], w2 = w2s[wid][t];
                a0x = fmaf(w0, hv.x, a0x); a0y = fmaf(w0, hv.y, a0y);
                a1x = fmaf(w1, hv.x, a1x); a1y = fmaf(w1, hv.y, a1y);
                a2x = fmaf(w2, hv.x, a2x); a2y = fmaf(w2, hv.y, a2y);
            }
        }
        __syncwarp();
    }

    const size_t o = (size_t)node * KF;
    ((float2*)(g + o      ))[lid] = make_float2(a0x, a0y);
    ((float2*)(g + o +  64))[lid] = make_float2(a1x, a1y);
    ((float2*)(g + o + 128))[lid] = make_float2(a2x, a2y);
}

// ---------------------------------------------------------------------------
// GEMM (chunked): out[i,f] = sum_p g[i,p] * Wk[p][f]  over rows [rs, re).
// 256 threads, tile 64 rows x 64 cols, thread tile 4x4.
// K-packed FFMA2: acc holds even/odd-p partial sums; both operands are
// contiguous u64 smem loads (no register duplication movs).
//   gs [64][196] row-major   (rows in a warp hit distinct banks: r*196*4)
//   WsT[64][196] W transposed (f-major), 2-way conflict worst case
// smem/CTA = 2*64*196*4 = 100352 B  -> 2 CTAs/SM, 16 warps/SM.
// ---------------------------------------------------------------------------
#define GST 196
#define GEMM_SMEM (2 * 64 * GST * 4)

__global__ __launch_bounds__(256, 2)
void gemm_kernel(const float* __restrict__ g,   // [n, 192]
                 const float* __restrict__ W,   // [64, 192]
                 float* __restrict__ out, int rs, int re)
{
    extern __shared__ float smem[];
    float* gs  = smem;              // [64][GST]
    float* WsT = smem + 64 * GST;   // [64][GST]  WsT[f][p] = Wk[p][f]

    const int tid = threadIdx.x;

    // Load transposed weights once: WsT[f][p], p=k*64+j -> W[j*192+k*64+f]
    for (int idx = tid; idx < 192 * 64; idx += 256) {
        const int f = idx & 63, p = idx >> 6;
        const int j = p & 63, k = p >> 6;
        WsT[f * GST + p] = __ldg(&W[j * 192 + k * 64 + f]);
    }

    const int tx = tid & 15;       // cols 4tx .. 4tx+3
    const int ty = tid >> 4;       // rows 4ty .. 4ty+3
    const int ty4 = ty << 2;

    const unsigned long long* wp0 = (const unsigned long long*)(WsT + (4*tx + 0) * GST);
    const unsigned long long* wp1 = (const unsigned long long*)(WsT + (4*tx + 1) * GST);
    const unsigned long long* wp2 = (const unsigned long long*)(WsT + (4*tx + 2) * GST);
    const unsigned long long* wp3 = (const unsigned long long*)(WsT + (4*tx + 3) * GST);
    const unsigned long long* gp0 = (const unsigned long long*)(gs + (ty4 + 0) * GST);
    const unsigned long long* gp1 = (const unsigned long long*)(gs + (ty4 + 1) * GST);
    const unsigned long long* gp2 = (const unsigned long long*)(gs + (ty4 + 2) * GST);
    const unsigned long long* gp3 = (const unsigned long long*)(gs + (ty4 + 3) * GST);

    const int ntiles = (re - rs + 63) >> 6;
    for (int tile = blockIdx.x; tile < ntiles; tile += gridDim.x) {
        const int r0 = rs + (tile << 6);
        const int rows = min(64, re - r0);
        __syncthreads();   // prev readers done; WsT ready on iter 0

        for (int idx = tid; idx < 64 * 48; idx += 256) {
            const int r = idx / 48, pc = idx - r * 48;
            float4 v = make_float4(0.f, 0.f, 0.f, 0.f);
            if (r < rows)
                v = __ldg((const float4*)(g + (size_t)(r0 + r) * KF) + pc);
            *(float4*)(gs + r * GST + 4 * pc) = v;
        }
        __syncthreads();

        unsigned long long acc[4][4];
        #pragma unroll
        for (int i = 0; i < 4; i++)
            #pragma unroll
            for (int c = 0; c < 4; c++) acc[i][c] = 0ULL;

        #pragma unroll 2
        for (int pp = 0; pp < 96; pp++) {
            const unsigned long long wa = wp0[pp], wb = wp1[pp],
                                     wc = wp2[pp], wd = wp3[pp];
            const unsigned long long g0 = gp0[pp], g1 = gp1[pp],
                                     g2 = gp2[pp], g3 = gp3[pp];
            FMA_F32X2(acc[0][0], g0, wa, acc[0][0]);
            FMA_F32X2(acc[0][1], g0, wb, acc[0][1]);
            FMA_F32X2(acc[0][2], g0, wc, acc[0][2]);
            FMA_F32X2(acc[0][3], g0, wd, acc[0][3]);
            FMA_F32X2(acc[1][0], g1, wa, acc[1][0]);
            FMA_F32X2(acc[1][1], g1, wb, acc[1][1]);
            FMA_F32X2(acc[1][2], g1, wc, acc[1][2]);
            FMA_F32X2(acc[1][3], g1, wd, acc[1][3]);
            FMA_F32X2(acc[2][0], g2, wa, acc[2][0]);
            FMA_F32X2(acc[2][1], g2, wb, acc[2][1]);
            FMA_F32X2(acc[2][2], g2, wc, acc[2][2]);
            FMA_F32X2(acc[2][3], g2, wd, acc[2][3]);
            FMA_F32X2(acc[3][0], g3, wa, acc[3][0]);
            FMA_F32X2(acc[3][1], g3, wb, acc[3][1]);
            FMA_F32X2(acc[3][2], g3, wc, acc[3][2]);
            FMA_F32X2(acc[3][3], g3, wd, acc[3][3]);
        }

        #pragma unroll
        for (int i = 0; i < 4; i++) {
            if (ty4 + i < rows) {
                float lo, hi, r0v, r1v, r2v, r3v;
                UNPACK2(lo, hi, acc[i][0]); r0v = lo + hi;
                UNPACK2(lo, hi, acc[i][1]); r1v = lo + hi;
                UNPACK2(lo, hi, acc[i][2]); r2v = lo + hi;
                UNPACK2(lo, hi, acc[i][3]); r3v = lo + hi;
                *(float4*)&out[(size_t)(r0 + ty4 + i) * FDIM + (tx << 2)] =
                    make_float4(r0v, r1v, r2v, r3v);
            }
        }
    }
}

// ---------------------------------------------------------------------------
static cudaStream_t g_side = (cudaStream_t)0;
static cudaEvent_t  g_evA[3][NCHUNK];
static cudaEvent_t  g_evG[3];
static int          g_inited = 0;

extern "C" void kernel_launch(void* const* d_in, const int* in_sizes, int n_in,
                              void* d_out, int out_size)
{
    const float* feat   = (const float*)d_in[0];
    const float* pseudo = (const float*)d_in[1];
    const int*   rowptr = (const int*)  d_in[2];
    const int*   colind = (const int*)  d_in[3];
    const float* projW  = (const float*)d_in[4];  // [L,2,2]
    const float* projb  = (const float*)d_in[5];  // [L,2]
    const float* fcW    = (const float*)d_in[6];  // [L,64,192]
    const float* mu     = (const float*)d_in[7];  // [L,3,2]
    const float* isg    = (const float*)d_in[8];  // [L,3,2]

    const int n  = in_sizes[0] / FDIM;
    const int nL = in_sizes[6] / (FDIM * KF);

    if (!g_inited) {               // host-side resource init on first
        g_inited = 1;              // (uncaptured) call; identical GPU work every call
        int lo = 0, hi = 0;
        cudaDeviceGetStreamPriorityRange(&lo, &hi);
        if (cudaStreamCreateWithPriority(&g_side, cudaStreamNonBlocking, hi) != cudaSuccess)
            g_side = (cudaStream_t)0;
        for (int i = 0; i < 3; i++) {
            for (int j = 0; j < NCHUNK; j++)
                cudaEventCreateWithFlags(&g_evA[i][j], cudaEventDisableTiming);
            cudaEventCreateWithFlags(&g_evG[i], cudaEventDisableTiming);
        }
    }

    void *gp, *hap, *hbp;
    cudaGetSymbolAddress(&gp,  g_buf);
    cudaGetSymbolAddress(&hap, h_bufA);
    cudaGetSymbolAddress(&hbp, h_bufB);
    float* gbuf = (float*)gp;
    float* hbufs[2] = { (float*)hap, (float*)hbp };

    cudaFuncSetAttribute(gemm_kernel, cudaFuncAttributeMaxDynamicSharedMemorySize, GEMM_SMEM);

    // chunk boundaries, multiples of 64
    int bnd[NCHUNK + 1];
    bnd[0] = 0;
    const int step = ((n + NCHUNK - 1) / NCHUNK + 63) & ~63;
    for (int j = 1; j < NCHUNK; j++) bnd[j] = min(n, j * step);
    bnd[NCHUNK] = n;

    const bool pipe = (g_side != (cudaStream_t)0) && nL <= 3;

    const float* hin = feat;
    for (int i = 0; i < nL; i++) {
        float* hout = (i == nL - 1) ? (float*)d_out : hbufs[i & 1];

        if (pipe) {
            for (int j = 0; j < NCHUNK; j++) {
                const int ns = bnd[j], ne = bnd[j + 1];
                if (ne <= ns) { cudaEventRecord(g_evA[i][j], 0); continue; }
                agg_kernel<<<(ne - ns + 7) / 8, 256>>>(hin, pseudo, rowptr, colind,
                                                       projW + i * 4, projb + i * 2,
                                                       mu + i * 6, isg + i * 6,
                                                       gbuf, ns, ne);
                cudaEventRecord(g_evA[i][j], 0);
            }
            for (int j = 0; j < NCHUNK; j++) {
                const int ns = bnd[j], ne = bnd[j + 1];
                cudaStreamWaitEvent(g_side, g_evA[i][j], 0);
                if (ne <= ns) continue;
                const int tiles = (ne - ns + 63) / 64;
                const int grid = tiles < 296 ? tiles : 296;
                gemm_kernel<<<grid, 256, GEMM_SMEM, g_side>>>(
                    gbuf, fcW + i * (FDIM * KF), hout, ns, ne);
            }
            cudaEventRecord(g_evG[i], g_side);
            cudaStreamWaitEvent((cudaStream_t)0, g_evG[i], 0);
        } else {
            agg_kernel<<<(n + 7) / 8, 256>>>(hin, pseudo, rowptr, colind,
                                             projW + i * 4, projb + i * 2,
                                             mu + i * 6, isg + i * 6,
                                             gbuf, 0, n);
            const int tiles = (n + 63) / 64;
            const int grid = tiles < 296 ? tiles : 296;
            gemm_kernel<<<grid, 256, GEMM_SMEM>>>(gbuf, fcW + i * (FDIM * KF), hout, 0, n);
        }
        hin = hout;
    }
}

// round 7
// speedup vs baseline: 1.5140x; 1.5140x over previous
#include <cuda_runtime.h>
#include <cuda_bf16.h>
#include <cstddef>

// Problem constants: N=50000, DEG=32, E=N*32, F=64, K=3, DIM=2, L=3
#define MAXN 50000
#define FDIM 64
#define KF   192        // K * F
#define NCHUNK 3

// Scratch (device globals — no allocation in kernel_launch)
__device__ float g_buf[(size_t)MAXN * KF];
__device__ float h_bufA[(size_t)MAXN * FDIM];
__device__ float h_bufB[(size_t)MAXN * FDIM];

// Packed fp32x2 FMA (sm_103a FFMA2 — only reachable via PTX)
#define FMA_F32X2(d, a, b, c) \
    asm("fma.rn.f32x2 %0, %1, %2, %3;" : "=l"(d) : "l"(a), "l"(b), "l"(c))
#define PACK_DUP(d, x) \
    asm("mov.b64 %0, {%1, %1};" : "=l"(d) : "f"(x))
#define UNPACK2(lo, hi, v) \
    asm("mov.b64 {%0, %1}, %2;" : "=f"(lo), "=f"(hi) : "l"(v))

// ---------------------------------------------------------------------------
// Aggregation kernel (chunked): one warp per destination node in [ns, ne).
//   g[i, k*64+f] = sum_e w_k(e) * h[colind[e], f]
// Proven at ~38us full-layer (L2 roofline: 410MB @ ~11TB/s LTS cap).
// ---------------------------------------------------------------------------
__global__ __launch_bounds__(256)
void agg_kernel(const float* __restrict__ h,
                const float* __restrict__ pseudo,   // [E,2]
                const int*   __restrict__ rowptr,   // [N+1]
                const int*   __restrict__ colind,   // [E]
                const float* __restrict__ pW,       // [2,2]
                const float* __restrict__ pb,       // [2]
                const float* __restrict__ mu,       // [K,2]
                const float* __restrict__ isg,      // [K,2]
                float* __restrict__ g, int ns, int ne)
{
    __shared__ float w0s[8][32], w1s[8][32], w2s[8][32];
    __shared__ int   ss[8][32];

    const int wid = threadIdx.x >> 5;
    const int lid = threadIdx.x & 31;
    const int node = ns + blockIdx.x * 8 + wid;
    if (node >= ne) return;

    const float W00 = pW[0], W01 = pW[1], W10 = pW[2], W11 = pW[3];
    const float b0 = pb[0], b1 = pb[1];
    const float m00 = mu[0], m01 = mu[1], m10 = mu[2], m11 = mu[3], m20 = mu[4], m21 = mu[5];
    const float s00 = isg[0]*isg[0], s01 = isg[1]*isg[1];
    const float s10 = isg[2]*isg[2], s11 = isg[3]*isg[3];
    const float s20 = isg[4]*isg[4], s21 = isg[5]*isg[5];

    const int e0 = rowptr[node], e1 = rowptr[node + 1];

    float a0x = 0.f, a0y = 0.f, a1x = 0.f, a1y = 0.f, a2x = 0.f, a2y = 0.f;
    const float2* __restrict__ ps2 = (const float2*)pseudo;

    for (int base = e0; base < e1; base += 32) {
        const int cnt = min(32, e1 - base);
        if (lid < cnt) {
            const int e = base + lid;
            float2 ps = __ldg(&ps2[e]);
            float u0 = tanhf(fmaf(ps.y, W10, fmaf(ps.x, W00, b0)));
            float u1 = tanhf(fmaf(ps.y, W11, fmaf(ps.x, W01, b1)));
            float d0, d1;
            d0 = u0 - m00; d1 = u1 - m01;
            w0s[wid][lid] = __expf(-0.5f * (d0*d0*s00 + d1*d1*s01));
            d0 = u0 - m10; d1 = u1 - m11;
            w1s[wid][lid] = __expf(-0.5f * (d0*d0*s10 + d1*d1*s11));
            d0 = u0 - m20; d1 = u1 - m21;
            w2s[wid][lid] = __expf(-0.5f * (d0*d0*s20 + d1*d1*s21));
            ss[wid][lid] = __ldg(&colind[e]);
        }
        __syncwarp();
        if (cnt == 32) {
            #pragma unroll 8
            for (int t = 0; t < 32; t++) {
                const float2 hv = __ldg((const float2*)(h + (size_t)ss[wid][t] * FDIM) + lid);
                const float w0 = w0s[wid][t], w1 = w1s[wid][t], w2 = w2s[wid][t];
                a0x = fmaf(w0, hv.x, a0x); a0y = fmaf(w0, hv.y, a0y);
                a1x = fmaf(w1, hv.x, a1x); a1y = fmaf(w1, hv.y, a1y);
                a2x = fmaf(w2, hv.x, a2x); a2y = fmaf(w2, hv.y, a2y);
            }
        } else {
            for (int t = 0; t < cnt; t++) {
                const float2 hv = __ldg((const float2*)(h + (size_t)ss[wid][t] * FDIM) + lid);
                const float w0 = w0s[wid][t], w1 = w1s[wid][t], w2 = w2s[wid][t];
                a0x = fmaf(w0, hv.x, a0x); a0y = fmaf(w0, hv.y, a0y);
                a1x = fmaf(w1, hv.x, a1x); a1y = fmaf(w1, hv.y, a1y);
                a2x = fmaf(w2, hv.x, a2x); a2y = fmaf(w2, hv.y, a2y);
            }
        }
        __syncwarp();
    }

    const size_t o = (size_t)node * KF;
    ((float2*)(g + o      ))[lid] = make_float2(a0x, a0y);
    ((float2*)(g + o +  64))[lid] = make_float2(a1x, a1y);
    ((float2*)(g + o + 128))[lid] = make_float2(a2x, a2y);
}

// ---------------------------------------------------------------------------
// GEMM (chunked): out[i,f] = sum_p g[i,p] * Wk[p][f]  over rows [rs, re).
// Round-3 proven formulation resized: 256 threads, tile 64x64, thread tile
// 4 rows (2 packed pairs) x 4 cols. Row-pair FFMA2 + XOR-swizzled transposed
// g tile (8-bank spread on transpose stores; broadcast-dedup'd W reads).
// smem: Ws[192][64] + gsT[192][64] = 96KB -> 2 CTAs/SM, 16 warps/SM.
// ---------------------------------------------------------------------------
#define GEMM_SMEM (2 * 192 * 64 * 4)   // 98304 B

__global__ __launch_bounds__(256, 2)
void gemm_kernel(const float* __restrict__ g,   // [n, 192]
                 const float* __restrict__ W,   // [64, 192]
                 float* __restrict__ out, int rs, int re)
{
    extern __shared__ float smem[];
    float* Ws  = smem;              // [192][64]  Ws[p*64+f]
    float* gsT = smem + 192 * 64;   // [192][64]  gsT[p*64 + swz(r)]

    const int tid = threadIdx.x;

    // Load weights once: Ws[p][f], p = k*64+j -> W[j*192 + k*64 + f]
    for (int idx = tid; idx < 192 * 64; idx += 256) {
        const int p = idx >> 6, f = idx & 63;
        const int j = p & 63, k = p >> 6;
        Ws[idx] = __ldg(&W[j * 192 + k * 64 + f]);
    }

    const int tx = tid & 15;       // cols 4tx..+3
    const int ty = tid >> 4;       // rows 4ty..+3
    const int ty4 = ty << 2;

    const int ntiles = (re - rs + 63) >> 6;
    for (int tile = blockIdx.x; tile < ntiles; tile += gridDim.x) {
        const int r0 = rs + (tile << 6);
        const int rows = min(64, re - r0);
        __syncthreads();   // prev readers done; Ws ready on iter 0

        // Transposed + swizzled tile load
        for (int idx = tid; idx < 64 * 48; idx += 256) {
            const int r = idx / 48, pc = idx - r * 48;
            float4 v = make_float4(0.f, 0.f, 0.f, 0.f);
            if (r < rows)
                v = __ldg((const float4*)(g + (size_t)(r0 + r) * KF) + pc);
            const int rsw = r ^ ((pc & 7) << 2);
            const int p = pc << 2;
            gsT[(p    ) * 64 + rsw] = v.x;
            gsT[(p + 1) * 64 + rsw] = v.y;
            gsT[(p + 2) * 64 + rsw] = v.z;
            gsT[(p + 3) * 64 + rsw] = v.w;
        }
        __syncthreads();

        // acc[i][c]: packed rows (ty4+2i, ty4+2i+1), col 4tx+c
        unsigned long long acc[2][4];
        #pragma unroll
        for (int i = 0; i < 2; i++)
            #pragma unroll
            for (int c = 0; c < 4; c++) acc[i][c] = 0ULL;

        #pragma unroll 4
        for (int p = 0; p < 192; p++) {
            const int b0r = ty4 ^ (((p >> 2) & 7) << 2);
            const ulonglong2 ga = *(const ulonglong2*)(gsT + p * 64 + b0r);
            const float4 wv = *(const float4*)(Ws + p * 64 + (tx << 2));
            unsigned long long w0, w1, w2, w3;
            PACK_DUP(w0, wv.x); PACK_DUP(w1, wv.y);
            PACK_DUP(w2, wv.z); PACK_DUP(w3, wv.w);
            FMA_F32X2(acc[0][0], ga.x, w0, acc[0][0]);
            FMA_F32X2(acc[0][1], ga.x, w1, acc[0][1]);
            FMA_F32X2(acc[0][2], ga.x, w2, acc[0][2]);
            FMA_F32X2(acc[0][3], ga.x, w3, acc[0][3]);
            FMA_F32X2(acc[1][0], ga.y, w0, acc[1][0]);
            FMA_F32X2(acc[1][1], ga.y, w1, acc[1][1]);
            FMA_F32X2(acc[1][2], ga.y, w2, acc[1][2]);
            FMA_F32X2(acc[1][3], ga.y, w3, acc[1][3]);
        }

        #pragma unroll
        for (int i = 0; i < 2; i++) {
            float lx, hx, ly, hy, lz, hz, lw, hw;
            UNPACK2(lx, hx, acc[i][0]);
            UNPACK2(ly, hy, acc[i][1]);
            UNPACK2(lz, hz, acc[i][2]);
            UNPACK2(lw, hw, acc[i][3]);
            const int rA = ty4 + 2 * i;
            if (rA < rows)
                *(float4*)&out[(size_t)(r0 + rA) * FDIM + (tx << 2)] =
                    make_float4(lx, ly, lz, lw);
            if (rA + 1 < rows)
                *(float4*)&out[(size_t)(r0 + rA + 1) * FDIM + (tx << 2)] =
                    make_float4(hx, hy, hz, hw);
        }
    }
}

// ---------------------------------------------------------------------------
static cudaStream_t g_side = (cudaStream_t)0;
static cudaEvent_t  g_evA[3][NCHUNK];
static cudaEvent_t  g_evG[3];
static int          g_inited = 0;

extern "C" void kernel_launch(void* const* d_in, const int* in_sizes, int n_in,
                              void* d_out, int out_size)
{
    const float* feat   = (const float*)d_in[0];
    const float* pseudo = (const float*)d_in[1];
    const int*   rowptr = (const int*)  d_in[2];
    const int*   colind = (const int*)  d_in[3];
    const float* projW  = (const float*)d_in[4];  // [L,2,2]
    const float* projb  = (const float*)d_in[5];  // [L,2]
    const float* fcW    = (const float*)d_in[6];  // [L,64,192]
    const float* mu     = (const float*)d_in[7];  // [L,3,2]
    const float* isg    = (const float*)d_in[8];  // [L,3,2]

    const int n  = in_sizes[0] / FDIM;
    const int nL = in_sizes[6] / (FDIM * KF);

    if (!g_inited) {               // host-side resource init on first
        g_inited = 1;              // (uncaptured) call; identical GPU work every call
        int lo = 0, hi = 0;
        cudaDeviceGetStreamPriorityRange(&lo, &hi);
        if (cudaStreamCreateWithPriority(&g_side, cudaStreamNonBlocking, hi) != cudaSuccess)
            g_side = (cudaStream_t)0;
        for (int i = 0; i < 3; i++) {
            for (int j = 0; j < NCHUNK; j++)
                cudaEventCreateWithFlags(&g_evA[i][j], cudaEventDisableTiming);
            cudaEventCreateWithFlags(&g_evG[i], cudaEventDisableTiming);
        }
    }

    void *gp, *hap, *hbp;
    cudaGetSymbolAddress(&gp,  g_buf);
    cudaGetSymbolAddress(&hap, h_bufA);
    cudaGetSymbolAddress(&hbp, h_bufB);
    float* gbuf = (float*)gp;
    float* hbufs[2] = { (float*)hap, (float*)hbp };

    cudaFuncSetAttribute(gemm_kernel, cudaFuncAttributeMaxDynamicSharedMemorySize, GEMM_SMEM);

    // chunk boundaries, multiples of 64
    int bnd[NCHUNK + 1];
    bnd[0] = 0;
    const int step = ((n + NCHUNK - 1) / NCHUNK + 63) & ~63;
    for (int j = 1; j < NCHUNK; j++) bnd[j] = min(n, j * step);
    bnd[NCHUNK] = n;

    const bool pipe = (g_side != (cudaStream_t)0) && nL <= 3;

    const float* hin = feat;
    for (int i = 0; i < nL; i++) {
        float* hout = (i == nL - 1) ? (float*)d_out : hbufs[i & 1];

        if (pipe) {
            for (int j = 0; j < NCHUNK; j++) {
                const int ns = bnd[j], ne = bnd[j + 1];
                if (ne <= ns) { cudaEventRecord(g_evA[i][j], 0); continue; }
                agg_kernel<<<(ne - ns + 7) / 8, 256>>>(hin, pseudo, rowptr, colind,
                                                       projW + i * 4, projb + i * 2,
                                                       mu + i * 6, isg + i * 6,
                                                       gbuf, ns, ne);
                cudaEventRecord(g_evA[i][j], 0);
            }
            for (int j = 0; j < NCHUNK; j++) {
                const int ns = bnd[j], ne = bnd[j + 1];
                cudaStreamWaitEvent(g_side, g_evA[i][j], 0);
                if (ne <= ns) continue;
                const int tiles = (ne - ns + 63) / 64;
                const int grid = tiles < 296 ? tiles : 296;
                gemm_kernel<<<grid, 256, GEMM_SMEM, g_side>>>(
                    gbuf, fcW + i * (FDIM * KF), hout, ns, ne);
            }
            cudaEventRecord(g_evG[i], g_side);
            cudaStreamWaitEvent((cudaStream_t)0, g_evG[i], 0);
        } else {
            agg_kernel<<<(n + 7) / 8, 256>>>(hin, pseudo, rowptr, colind,
                                             projW + i * 4, projb + i * 2,
                                             mu + i * 6, isg + i * 6,
                                             gbuf, 0, n);
            const int tiles = (n + 63) / 64;
            const int grid = tiles < 296 ? tiles : 296;
            gemm_kernel<<<grid, 256, GEMM_SMEM>>>(gbuf, fcW + i * (FDIM * KF), hout, 0, n);
        }
        hin = hout;
    }
}

// round 8
// speedup vs baseline: 1.7325x; 1.1443x over previous
#include <cuda_runtime.h>
#include <cuda_bf16.h>
#include <cstddef>

// Problem constants: N=50000, DEG=32, E=N*32, F=64, K=3, DIM=2, L=3
#define MAXN 50000
#define FDIM 64
#define KF   192        // K * F
#define TILE 64

// smem: gs[64][192] row-major + wf4[8][32] float4 staging
#define GS_FLOATS (TILE * KF)
#define SMEM_FLOATS (GS_FLOATS + 8 * 32 * 4)
#define SMEM_BYTES  (SMEM_FLOATS * 4)      // 53248 B -> 3+ CTAs/SM

__device__ float h_bufA[(size_t)MAXN * FDIM];
__device__ float h_bufB[(size_t)MAXN * FDIM];
// WP[layer][pp][t] float4 = {Wk[2pp][2t], Wk[2pp+1][2t], Wk[2pp][2t+1], Wk[2pp+1][2t+1]}
__device__ float WP_buf[3 * 96 * 32 * 4];

// Packed fp32x2 FMA (sm_103a FFMA2 — only reachable via PTX)
#define FMA_F32X2(d, a, b, c) \
    asm("fma.rn.f32x2 %0, %1, %2, %3;" : "=l"(d) : "l"(a), "l"(b), "l"(c))
#define PACK_DUP(d, x) \
    asm("mov.b64 %0, {%1, %1};" : "=l"(d) : "f"(x))
#define UNPACK2(lo, hi, v) \
    asm("mov.b64 {%0, %1}, %2;" : "=f"(lo), "=f"(hi) : "l"(v))

// ---------------------------------------------------------------------------
// Prep: rearrange fcW into WP layout (K-pair-packed, warp-coalesced).
//   Wk[p][c] = fcW[j*192 + k*64 + c],  p = k*64 + j
// ---------------------------------------------------------------------------
__global__ void prep_kernel(const float* __restrict__ fcW, int nL)
{
    const int idx = blockIdx.x * 256 + threadIdx.x;   // one float4 per thread
    const int total = nL * 96 * 32;
    if (idx >= total) return;
    const int i  = idx / (96 * 32);
    const int rem = idx - i * 96 * 32;
    const int pp = rem >> 5, t = rem & 31;
    const float* W = fcW + i * 64 * 192;
    const int p0 = 2 * pp, p1 = 2 * pp + 1;
    const int k0 = p0 >> 6, j0 = p0 & 63;
    const int k1 = p1 >> 6, j1 = p1 & 63;
    float4 v;
    v.x = W[j0 * 192 + k0 * 64 + 2 * t];
    v.y = W[j1 * 192 + k1 * 64 + 2 * t];
    v.z = W[j0 * 192 + k0 * 64 + 2 * t + 1];
    v.w = W[j1 * 192 + k1 * 64 + 2 * t + 1];
    ((float4*)WP_buf)[idx] = v;
}

// ---------------------------------------------------------------------------
// Fused layer kernel (bulk-sync, proven round-4 structure, 3 CTAs/SM):
//   phase A: 8 warps x 8 nodes -> gs[r][p] row-major (packed FFMA2 gather)
//   phase B: block GEMM, g broadcast from smem + W coalesced LDG.128 (L1)
// ---------------------------------------------------------------------------
__global__ __launch_bounds__(256, 3)
void fused_layer(const float* __restrict__ h,
                 const float* __restrict__ pseudo,   // [E,2]
                 const int*   __restrict__ rowptr,   // [N+1]
                 const int*   __restrict__ colind,   // [E]
                 const float* __restrict__ pW,       // [2,2]
                 const float* __restrict__ pb,       // [2]
                 const float* __restrict__ mu,       // [K,2]
                 const float* __restrict__ isg,      // [K,2]
                 const float* __restrict__ WP,       // [96][32] float4
                 float* __restrict__ out, int n)
{
    extern __shared__ float smem[];
    float* gs = smem;                               // [64][192]
    float4* wf4 = (float4*)(smem + GS_FLOATS);      // [8][32]

    const int tid = threadIdx.x;
    const int wid = tid >> 5;
    const int lid = tid & 31;

    const float2* __restrict__ ps2 = (const float2*)pseudo;
    const ulonglong2* __restrict__ wpv = (const ulonglong2*)WP;

    // phase-B thread mapping
    const int tx = tid & 31;   // cols 2tx, 2tx+1
    const int ty = tid >> 5;   // rows 8ty .. +7

    const int ntiles = (n + TILE - 1) / TILE;
    for (int tile = blockIdx.x; tile < ntiles; tile += gridDim.x) {
        const int r0 = tile * TILE;
        const int rows = min(TILE, n - r0);
        __syncthreads();   // prev phase-B readers done

        // ---------------- Phase A: aggregation --------------------------
        {
            // load scalar params here so they are not live through phase B
            const float W00 = __ldg(&pW[0]), W01 = __ldg(&pW[1]);
            const float W10 = __ldg(&pW[2]), W11 = __ldg(&pW[3]);
            const float b0 = __ldg(&pb[0]), b1 = __ldg(&pb[1]);
            const float m00 = __ldg(&mu[0]), m01 = __ldg(&mu[1]);
            const float m10 = __ldg(&mu[2]), m11 = __ldg(&mu[3]);
            const float m20 = __ldg(&mu[4]), m21 = __ldg(&mu[5]);
            float t0 = __ldg(&isg[0]), t1 = __ldg(&isg[1]);
            const float s00 = t0*t0, s01 = t1*t1;
            t0 = __ldg(&isg[2]); t1 = __ldg(&isg[3]);
            const float s10 = t0*t0, s11 = t1*t1;
            t0 = __ldg(&isg[4]); t1 = __ldg(&isg[5]);
            const float s20 = t0*t0, s21 = t1*t1;

            float4* wfw = wf4 + (wid << 5);

            for (int j = 0; j < 8; j++) {
                const int r = (wid << 3) + j;
                const int node = r0 + r;
                if (node >= n) break;

                const int e0 = rowptr[node], e1 = rowptr[node + 1];
                unsigned long long A0 = 0ULL, A1 = 0ULL, A2 = 0ULL;

                for (int base = e0; base < e1; base += 32) {
                    const int cnt = min(32, e1 - base);
                    if (lid < cnt) {
                        const int e = base + lid;
                        float2 ps = __ldg(&ps2[e]);
                        float u0 = tanhf(fmaf(ps.y, W10, fmaf(ps.x, W00, b0)));
                        float u1 = tanhf(fmaf(ps.y, W11, fmaf(ps.x, W01, b1)));
                        float d0 = u0 - m00, d1 = u1 - m01;
                        float w0 = __expf(-0.5f * (d0*d0*s00 + d1*d1*s01));
                        d0 = u0 - m10; d1 = u1 - m11;
                        float w1 = __expf(-0.5f * (d0*d0*s10 + d1*d1*s11));
                        d0 = u0 - m20; d1 = u1 - m21;
                        float w2 = __expf(-0.5f * (d0*d0*s20 + d1*d1*s21));
                        wfw[lid] = make_float4(w0, w1, w2,
                                               __int_as_float(__ldg(&colind[e])));
                    }
                    __syncwarp();
                    #pragma unroll 8
                    for (int t = 0; t < cnt; t++) {
                        const float4 wt = wfw[t];
                        const int src = __float_as_int(wt.w);
                        const unsigned long long hv =
                            *(const unsigned long long*)(h + (size_t)src * FDIM + 2 * lid);
                        unsigned long long w0d, w1d, w2d;
                        PACK_DUP(w0d, wt.x); PACK_DUP(w1d, wt.y); PACK_DUP(w2d, wt.z);
                        FMA_F32X2(A0, hv, w0d, A0);
                        FMA_F32X2(A1, hv, w1d, A1);
                        FMA_F32X2(A2, hv, w2d, A2);
                    }
                    __syncwarp();
                }
                // row-major: gs[r][2lid..+1] per kernel block
                *(unsigned long long*)(gs + r * KF + 2 * lid      ) = A0;
                *(unsigned long long*)(gs + r * KF + 2 * lid +  64) = A1;
                *(unsigned long long*)(gs + r * KF + 2 * lid + 128) = A2;
            }
        }
        __syncthreads();

        // ---------------- Phase B: GEMM ---------------------------------
        {
            const unsigned long long* gp =
                (const unsigned long long*)(gs + (ty << 3) * KF);

            unsigned long long acc[8][2];
            #pragma unroll
            for (int i = 0; i < 8; i++) { acc[i][0] = 0ULL; acc[i][1] = 0ULL; }

            #pragma unroll 4
            for (int pp = 0; pp < 96; pp++) {
                const ulonglong2 w = __ldg(&wpv[pp * 32 + tx]);
                #pragma unroll
                for (int i = 0; i < 8; i++) {
                    const unsigned long long gv = gp[i * 96 + pp];
                    FMA_F32X2(acc[i][0], gv, w.x, acc[i][0]);
                    FMA_F32X2(acc[i][1], gv, w.y, acc[i][1]);
                }
            }

            #pragma unroll
            for (int i = 0; i < 8; i++) {
                const int r = (ty << 3) + i;
                if (r < rows) {
                    float e0, o0, e1, o1;
                    UNPACK2(e0, o0, acc[i][0]);
                    UNPACK2(e1, o1, acc[i][1]);
                    *(float2*)&out[(size_t)(r0 + r) * FDIM + 2 * tx] =
                        make_float2(e0 + o0, e1 + o1);
                }
            }
        }
    }
}

// ---------------------------------------------------------------------------
extern "C" void kernel_launch(void* const* d_in, const int* in_sizes, int n_in,
                              void* d_out, int out_size)
{
    const float* feat   = (const float*)d_in[0];
    const float* pseudo = (const float*)d_in[1];
    const int*   rowptr = (const int*)  d_in[2];
    const int*   colind = (const int*)  d_in[3];
    const float* projW  = (const float*)d_in[4];  // [L,2,2]
    const float* projb  = (const float*)d_in[5];  // [L,2]
    const float* fcW    = (const float*)d_in[6];  // [L,64,192]
    const float* mu     = (const float*)d_in[7];  // [L,3,2]
    const float* isg    = (const float*)d_in[8];  // [L,3,2]

    const int n  = in_sizes[0] / FDIM;
    const int nL = in_sizes[6] / (FDIM * KF);

    void *hap, *hbp, *wpp;
    cudaGetSymbolAddress(&hap, h_bufA);
    cudaGetSymbolAddress(&hbp, h_bufB);
    cudaGetSymbolAddress(&wpp, WP_buf);
    float* hbufs[2] = { (float*)hap, (float*)hbp };
    const float* WP = (const float*)wpp;

    cudaFuncSetAttribute(fused_layer, cudaFuncAttributeMaxDynamicSharedMemorySize, SMEM_BYTES);

    // prep: rearrange weights for all layers
    const int ptotal = nL * 96 * 32;
    prep_kernel<<<(ptotal + 255) / 256, 256>>>(fcW, nL);

    const int ntiles = (n + TILE - 1) / TILE;
    const int grid = ntiles < 444 ? ntiles : 444;   // 3 CTAs/SM persistent

    const float* hin = feat;
    for (int i = 0; i < nL; i++) {
        float* hout = (i == nL - 1) ? (float*)d_out : hbufs[i & 1];
        fused_layer<<<grid, 256, SMEM_BYTES>>>(hin, pseudo, rowptr, colind,
                                               projW + i * 4, projb + i * 2,
                                               mu + i * 6, isg + i * 6,
                                               WP + (size_t)i * 96 * 32 * 4,
                                               hout, n);
        hin = hout;
    }
}